// round 4
// baseline (speedup 1.0000x reference)
#include <cuda_runtime.h>
#include <math.h>
#include <stdint.h>

#define Bq  2
#define Sq  2048
#define Dq  1024
#define Hq  16
#define HDq 64

__device__ float g_qkv[(size_t)Bq * Sq * 3 * Dq];
__device__ float g_vals[(size_t)Bq * Sq * Dq];

// ---------------------------------------------------------------------------
__device__ __forceinline__ uint32_t f2tf32(float x) {
    uint32_t r;
    asm("cvt.rna.tf32.f32 %0, %1;" : "=r"(r) : "f"(x));
    return r;
}

__device__ __forceinline__ void mma_tf32(float c[4],
                                         uint32_t a0, uint32_t a1, uint32_t a2, uint32_t a3,
                                         uint32_t b0, uint32_t b1) {
    asm volatile(
        "mma.sync.aligned.m16n8k8.row.col.f32.tf32.tf32.f32 "
        "{%0,%1,%2,%3}, {%4,%5,%6,%7}, {%8,%9}, {%0,%1,%2,%3};"
        : "+f"(c[0]), "+f"(c[1]), "+f"(c[2]), "+f"(c[3])
        : "r"(a0), "r"(a1), "r"(a2), "r"(a3), "r"(b0), "r"(b1));
}

// ---------------------------------------------------------------------------
// tf32 GEMM with register-prefetch pipelining.
// C[M,N] = A[M,K] @ W[N,K]^T + bias[N]. BM=BN=128, BK=32, 256 thr, warp 64x32.
// ---------------------------------------------------------------------------
__global__ void __launch_bounds__(256)
gemm_tf32_nt_bias(int M, int N, int K,
                  const float* __restrict__ A,
                  const float* __restrict__ W,
                  const float* __restrict__ bias,
                  float* __restrict__ C)
{
    constexpr int BK = 32, PITCH = 36;
    __shared__ uint32_t As[128][PITCH];
    __shared__ uint32_t Ws[128][PITCH];

    const int tid  = threadIdx.x;
    const int lane = tid & 31;
    const int w    = tid >> 5;
    const int wr   = w >> 2;
    const int wc   = w & 3;
    const int m0   = blockIdx.y * 128;
    const int n0   = blockIdx.x * 128;
    const int g    = lane >> 2;
    const int tq   = lane & 3;

    const int lrow = tid >> 3;
    const int lc4  = (tid & 7) << 2;

    float acc[4][4][4];
#pragma unroll
    for (int i = 0; i < 4; i++)
#pragma unroll
        for (int j = 0; j < 4; j++)
#pragma unroll
            for (int e = 0; e < 4; e++) acc[i][j][e] = 0.0f;

    float4 av[4], wv[4];
    const float* Ap = A + (size_t)(m0 + lrow) * K + lc4;
    const float* Wp = W + (size_t)(n0 + lrow) * K + lc4;

    // prologue: load k0=0
#pragma unroll
    for (int rr = 0; rr < 4; rr++) {
        av[rr] = *(const float4*)(Ap + (size_t)rr * 32 * K);
        wv[rr] = *(const float4*)(Wp + (size_t)rr * 32 * K);
    }
#pragma unroll
    for (int rr = 0; rr < 4; rr++) {
        const int r = lrow + rr * 32;
        As[r][lc4 + 0] = f2tf32(av[rr].x); As[r][lc4 + 1] = f2tf32(av[rr].y);
        As[r][lc4 + 2] = f2tf32(av[rr].z); As[r][lc4 + 3] = f2tf32(av[rr].w);
        Ws[r][lc4 + 0] = f2tf32(wv[rr].x); Ws[r][lc4 + 1] = f2tf32(wv[rr].y);
        Ws[r][lc4 + 2] = f2tf32(wv[rr].z); Ws[r][lc4 + 3] = f2tf32(wv[rr].w);
    }
    __syncthreads();

    const int nIter = K / BK;
    for (int it = 0; it < nIter; it++) {
        // prefetch next tile into registers
        if (it + 1 < nIter) {
            const int ko = (it + 1) * BK;
#pragma unroll
            for (int rr = 0; rr < 4; rr++) {
                av[rr] = *(const float4*)(Ap + (size_t)rr * 32 * K + ko);
                wv[rr] = *(const float4*)(Wp + (size_t)rr * 32 * K + ko);
            }
        }

#pragma unroll
        for (int ks = 0; ks < 4; ks++) {
            const int kk = ks * 8;
            uint32_t af[4][4];
#pragma unroll
            for (int mi = 0; mi < 4; mi++) {
                const int rb = wr * 64 + mi * 16;
                af[mi][0] = As[rb + g    ][kk + tq    ];
                af[mi][1] = As[rb + g + 8][kk + tq    ];
                af[mi][2] = As[rb + g    ][kk + tq + 4];
                af[mi][3] = As[rb + g + 8][kk + tq + 4];
            }
            uint32_t bf[4][2];
#pragma unroll
            for (int ni = 0; ni < 4; ni++) {
                const int cb = wc * 32 + ni * 8;
                bf[ni][0] = Ws[cb + g][kk + tq    ];
                bf[ni][1] = Ws[cb + g][kk + tq + 4];
            }
#pragma unroll
            for (int mi = 0; mi < 4; mi++)
#pragma unroll
                for (int ni = 0; ni < 4; ni++)
                    mma_tf32(acc[mi][ni],
                             af[mi][0], af[mi][1], af[mi][2], af[mi][3],
                             bf[ni][0], bf[ni][1]);
        }

        if (it + 1 < nIter) {
            __syncthreads();
#pragma unroll
            for (int rr = 0; rr < 4; rr++) {
                const int r = lrow + rr * 32;
                As[r][lc4 + 0] = f2tf32(av[rr].x); As[r][lc4 + 1] = f2tf32(av[rr].y);
                As[r][lc4 + 2] = f2tf32(av[rr].z); As[r][lc4 + 3] = f2tf32(av[rr].w);
                Ws[r][lc4 + 0] = f2tf32(wv[rr].x); Ws[r][lc4 + 1] = f2tf32(wv[rr].y);
                Ws[r][lc4 + 2] = f2tf32(wv[rr].z); Ws[r][lc4 + 3] = f2tf32(wv[rr].w);
            }
            __syncthreads();
        }
    }

#pragma unroll
    for (int mi = 0; mi < 4; mi++) {
        const int r0 = m0 + wr * 64 + mi * 16 + g;
#pragma unroll
        for (int ni = 0; ni < 4; ni++) {
            const int c = n0 + wc * 32 + ni * 8 + 2 * tq;
            const float b0v = bias[c], b1v = bias[c + 1];
            float2 o0 = make_float2(acc[mi][ni][0] + b0v, acc[mi][ni][1] + b1v);
            float2 o1 = make_float2(acc[mi][ni][2] + b0v, acc[mi][ni][3] + b1v);
            *(float2*)(C + (size_t)r0 * N + c)       = o0;
            *(float2*)(C + (size_t)(r0 + 8) * N + c) = o1;
        }
    }
}

// ---------------------------------------------------------------------------
// Flash attention tf32: 256 threads (8 warps), 128 q rows per block, 64-key
// tiles, Q fragments register-resident, K/V register-prefetch pipelined.
// ---------------------------------------------------------------------------
#define QP 68
#define VP 72

__global__ void __launch_bounds__(256)
flash_attn_tf32(const float* __restrict__ qkv,
                const float* __restrict__ mask,
                float* __restrict__ out)
{
    extern __shared__ uint32_t sm[];
    uint32_t* QPs = sm;                      // [128][QP]: Q tile, then reused as P
    uint32_t* Ks  = sm + 128 * QP;           // [64][QP]
    uint32_t* Vs  = sm + 128 * QP + 64 * QP; // [64][VP]

    const int tid  = threadIdx.x;
    const int lane = tid & 31;
    const int w    = tid >> 5;
    const int g    = lane >> 2;
    const int tq   = lane & 3;

    const int q0 = blockIdx.x * 128;
    const int h  = blockIdx.y;
    const int b  = blockIdx.z;
    const float scale = 0.125f;

    const float* base = qkv + (size_t)b * Sq * (3 * Dq) + (size_t)h * (3 * HDq);

    // ---- Load Q tile (128x64) into smem as tf32 ----
    {
        const int r  = tid >> 4;
        const int c4 = (tid & 15) << 2;
#pragma unroll
        for (int rr = 0; rr < 8; rr++) {
            const int row = r + rr * 16;
            float4 v = *(const float4*)(base + (size_t)(q0 + row) * (3 * Dq) + c4);
            QPs[row * QP + c4 + 0] = f2tf32(v.x);
            QPs[row * QP + c4 + 1] = f2tf32(v.y);
            QPs[row * QP + c4 + 2] = f2tf32(v.z);
            QPs[row * QP + c4 + 3] = f2tf32(v.w);
        }
    }
    __syncthreads();

    // ---- Extract Q fragments (register-resident) ----
    uint32_t qa[8][4];
    {
        const int mb = w * 16;
#pragma unroll
        for (int ks = 0; ks < 8; ks++) {
            const int kk = ks * 8;
            qa[ks][0] = QPs[(mb + g)     * QP + kk + tq];
            qa[ks][1] = QPs[(mb + g + 8) * QP + kk + tq];
            qa[ks][2] = QPs[(mb + g)     * QP + kk + tq + 4];
            qa[ks][3] = QPs[(mb + g + 8) * QP + kk + tq + 4];
        }
    }
    __syncthreads();   // everyone done reading Q before QPs is reused as P

    float Oacc[8][4];
#pragma unroll
    for (int ni = 0; ni < 8; ni++)
#pragma unroll
        for (int e = 0; e < 4; e++) Oacc[ni][e] = 0.0f;
    float mrow0 = -INFINITY, mrow1 = -INFINITY;
    float lrow0 = 0.0f, lrow1 = 0.0f;

    const int r0 = w * 16 + g;
    const int r1 = r0 + 8;

    const int kvr  = tid >> 4;
    const int kvc4 = (tid & 15) << 2;
    float4 kr[4], vr[4];

    // prologue: load k-tile 0
#pragma unroll
    for (int rr = 0; rr < 4; rr++) {
        const int row = kvr + rr * 16;
        kr[rr] = *(const float4*)(base + 64  + (size_t)row * (3 * Dq) + kvc4);
        vr[rr] = *(const float4*)(base + 128 + (size_t)row * (3 * Dq) + kvc4);
    }
#pragma unroll
    for (int rr = 0; rr < 4; rr++) {
        const int row = kvr + rr * 16;
        Ks[row * QP + kvc4 + 0] = f2tf32(kr[rr].x);
        Ks[row * QP + kvc4 + 1] = f2tf32(kr[rr].y);
        Ks[row * QP + kvc4 + 2] = f2tf32(kr[rr].z);
        Ks[row * QP + kvc4 + 3] = f2tf32(kr[rr].w);
        Vs[row * VP + kvc4 + 0] = f2tf32(vr[rr].x);
        Vs[row * VP + kvc4 + 1] = f2tf32(vr[rr].y);
        Vs[row * VP + kvc4 + 2] = f2tf32(vr[rr].z);
        Vs[row * VP + kvc4 + 3] = f2tf32(vr[rr].w);
    }
    __syncthreads();

    constexpr int NT = Sq / 64;
    for (int kt = 0; kt < NT; kt++) {
        const int k0t = kt * 64;

        // prefetch next K/V tile into registers (FIX: + kvc4 column offset)
        if (kt + 1 < NT) {
#pragma unroll
            for (int rr = 0; rr < 4; rr++) {
                const size_t rbase =
                    (size_t)(k0t + 64 + kvr + rr * 16) * (3 * Dq) + kvc4;
                kr[rr] = *(const float4*)(base + 64  + rbase);
                vr[rr] = *(const float4*)(base + 128 + rbase);
            }
        }

        // ---- S = Q K^T ----
        float Sacc[8][4];
#pragma unroll
        for (int ni = 0; ni < 8; ni++)
#pragma unroll
            for (int e = 0; e < 4; e++) Sacc[ni][e] = 0.0f;

#pragma unroll
        for (int ks = 0; ks < 8; ks++) {
            const int kk = ks * 8;
#pragma unroll
            for (int ni = 0; ni < 8; ni++) {
                const int nb = ni * 8;
                uint32_t b0 = Ks[(nb + g) * QP + kk + tq];
                uint32_t b1 = Ks[(nb + g) * QP + kk + tq + 4];
                mma_tf32(Sacc[ni], qa[ks][0], qa[ks][1], qa[ks][2], qa[ks][3], b0, b1);
            }
        }

        // ---- scale + mask + online softmax ----
        float rmax0 = -INFINITY, rmax1 = -INFINITY;
#pragma unroll
        for (int ni = 0; ni < 8; ni++) {
            const int c = ni * 8 + 2 * tq;
            float2 mk0 = *(const float2*)(mask + (size_t)(q0 + r0) * Sq + k0t + c);
            float2 mk1 = *(const float2*)(mask + (size_t)(q0 + r1) * Sq + k0t + c);
            Sacc[ni][0] = Sacc[ni][0] * scale + mk0.x;
            Sacc[ni][1] = Sacc[ni][1] * scale + mk0.y;
            Sacc[ni][2] = Sacc[ni][2] * scale + mk1.x;
            Sacc[ni][3] = Sacc[ni][3] * scale + mk1.y;
            rmax0 = fmaxf(rmax0, fmaxf(Sacc[ni][0], Sacc[ni][1]));
            rmax1 = fmaxf(rmax1, fmaxf(Sacc[ni][2], Sacc[ni][3]));
        }
#pragma unroll
        for (int off = 1; off < 4; off <<= 1) {
            rmax0 = fmaxf(rmax0, __shfl_xor_sync(0xffffffffu, rmax0, off));
            rmax1 = fmaxf(rmax1, __shfl_xor_sync(0xffffffffu, rmax1, off));
        }
        const float mnew0 = fmaxf(mrow0, rmax0);
        const float mnew1 = fmaxf(mrow1, rmax1);
        const float alpha0 = __expf(mrow0 - mnew0);
        const float alpha1 = __expf(mrow1 - mnew1);
        float rs0 = 0.0f, rs1 = 0.0f;
#pragma unroll
        for (int ni = 0; ni < 8; ni++) {
            Sacc[ni][0] = __expf(Sacc[ni][0] - mnew0);
            Sacc[ni][1] = __expf(Sacc[ni][1] - mnew0);
            Sacc[ni][2] = __expf(Sacc[ni][2] - mnew1);
            Sacc[ni][3] = __expf(Sacc[ni][3] - mnew1);
            rs0 += Sacc[ni][0] + Sacc[ni][1];
            rs1 += Sacc[ni][2] + Sacc[ni][3];
        }
#pragma unroll
        for (int off = 1; off < 4; off <<= 1) {
            rs0 += __shfl_xor_sync(0xffffffffu, rs0, off);
            rs1 += __shfl_xor_sync(0xffffffffu, rs1, off);
        }
        lrow0 = lrow0 * alpha0 + rs0;
        lrow1 = lrow1 * alpha1 + rs1;
        mrow0 = mnew0;
        mrow1 = mnew1;
#pragma unroll
        for (int ni = 0; ni < 8; ni++) {
            Oacc[ni][0] *= alpha0; Oacc[ni][1] *= alpha0;
            Oacc[ni][2] *= alpha1; Oacc[ni][3] *= alpha1;
        }

        // ---- stash P into this warp's private rows of QPs ----
        const int qr0 = w * 16 + g;
#pragma unroll
        for (int ni = 0; ni < 8; ni++) {
            const int c = ni * 8 + 2 * tq;
            uint2 s0 = make_uint2(f2tf32(Sacc[ni][0]), f2tf32(Sacc[ni][1]));
            uint2 s1 = make_uint2(f2tf32(Sacc[ni][2]), f2tf32(Sacc[ni][3]));
            *(uint2*)(QPs + (qr0)     * QP + c) = s0;
            *(uint2*)(QPs + (qr0 + 8) * QP + c) = s1;
        }
        __syncwarp();

        // ---- O += P V ----
        const int mb = w * 16;
#pragma unroll
        for (int ks = 0; ks < 8; ks++) {
            const int kk = ks * 8;
            uint32_t a0 = QPs[(mb + g)     * QP + kk + tq];
            uint32_t a1 = QPs[(mb + g + 8) * QP + kk + tq];
            uint32_t a2 = QPs[(mb + g)     * QP + kk + tq + 4];
            uint32_t a3 = QPs[(mb + g + 8) * QP + kk + tq + 4];
#pragma unroll
            for (int ni = 0; ni < 8; ni++) {
                const int nb = ni * 8;
                uint32_t b0 = Vs[(kk + tq)     * VP + nb + g];
                uint32_t b1 = Vs[(kk + tq + 4) * VP + nb + g];
                mma_tf32(Oacc[ni], a0, a1, a2, a3, b0, b1);
            }
        }

        // ---- commit prefetched K/V tile to smem ----
        if (kt + 1 < NT) {
            __syncthreads();
#pragma unroll
            for (int rr = 0; rr < 4; rr++) {
                const int row = kvr + rr * 16;
                Ks[row * QP + kvc4 + 0] = f2tf32(kr[rr].x);
                Ks[row * QP + kvc4 + 1] = f2tf32(kr[rr].y);
                Ks[row * QP + kvc4 + 2] = f2tf32(kr[rr].z);
                Ks[row * QP + kvc4 + 3] = f2tf32(kr[rr].w);
                Vs[row * VP + kvc4 + 0] = f2tf32(vr[rr].x);
                Vs[row * VP + kvc4 + 1] = f2tf32(vr[rr].y);
                Vs[row * VP + kvc4 + 2] = f2tf32(vr[rr].z);
                Vs[row * VP + kvc4 + 3] = f2tf32(vr[rr].w);
            }
            __syncthreads();
        }
    }

    // ---- epilogue ----
    const float inv0 = 1.0f / lrow0;
    const float inv1 = 1.0f / lrow1;
    float* obase = out + (size_t)b * Sq * Dq + (size_t)h * HDq;
#pragma unroll
    for (int ni = 0; ni < 8; ni++) {
        const int c = ni * 8 + 2 * tq;
        float2 o0 = make_float2(Oacc[ni][0] * inv0, Oacc[ni][1] * inv0);
        float2 o1 = make_float2(Oacc[ni][2] * inv1, Oacc[ni][3] * inv1);
        *(float2*)(obase + (size_t)(q0 + r0) * Dq + c) = o0;
        *(float2*)(obase + (size_t)(q0 + r1) * Dq + c) = o1;
    }
}

// ---------------------------------------------------------------------------
extern "C" void kernel_launch(void* const* d_in, const int* in_sizes, int n_in,
                              void* d_out, int out_size)
{
    const float* x    = (const float*)d_in[0];
    const float* mask = (const float*)d_in[1];
    const float* Wqkv = (const float*)d_in[2];
    const float* bqkv = (const float*)d_in[3];
    const float* Wo   = (const float*)d_in[4];
    const float* bo   = (const float*)d_in[5];
    float* out = (float*)d_out;

    float* qkv  = nullptr;
    float* vals = nullptr;
    cudaGetSymbolAddress((void**)&qkv,  g_qkv);
    cudaGetSymbolAddress((void**)&vals, g_vals);

    // 1) QKV projection
    {
        dim3 grid((3 * Dq) / 128, (Bq * Sq) / 128);
        gemm_tf32_nt_bias<<<grid, 256>>>(Bq * Sq, 3 * Dq, Dq, x, Wqkv, bqkv, qkv);
    }

    // 2) Flash attention
    {
        const int smem = (128 * QP + 64 * QP + 64 * VP) * (int)sizeof(uint32_t); // 70656 B
        cudaFuncSetAttribute(flash_attn_tf32,
                             cudaFuncAttributeMaxDynamicSharedMemorySize, smem);
        dim3 grid(Sq / 128, Hq, Bq);
        flash_attn_tf32<<<grid, 256, smem>>>(qkv, mask, vals);
    }

    // 3) Output projection
    {
        dim3 grid(Dq / 128, (Bq * Sq) / 128);
        gemm_tf32_nt_bias<<<grid, 256>>>(Bq * Sq, Dq, Dq, vals, Wo, bo, out);
    }
}

// round 5
// speedup vs baseline: 1.0128x; 1.0128x over previous
#include <cuda_runtime.h>
#include <math.h>
#include <stdint.h>

#define Bq  2
#define Sq  2048
#define Dq  1024
#define Hq  16
#define HDq 64

__device__ float g_qkv[(size_t)Bq * Sq * 3 * Dq];   // tf32-rounded Q,K,V
__device__ float g_vals[(size_t)Bq * Sq * Dq];      // tf32-rounded attn out
__device__ float g_xc[(size_t)Bq * Sq * Dq];        // tf32-rounded x
__device__ float g_wqkvc[(size_t)3 * Dq * Dq];      // tf32-rounded Wqkv
__device__ float g_woc[(size_t)Dq * Dq];            // tf32-rounded Wo

// ---------------------------------------------------------------------------
__device__ __forceinline__ uint32_t f2tf32(float x) {
    uint32_t r;
    asm("cvt.rna.tf32.f32 %0, %1;" : "=r"(r) : "f"(x));
    return r;
}
__device__ __forceinline__ float roundtf(float x) {
    return __uint_as_float(f2tf32(x));
}

__device__ __forceinline__ void mma_tf32(float c[4],
                                         uint32_t a0, uint32_t a1, uint32_t a2, uint32_t a3,
                                         uint32_t b0, uint32_t b1) {
    asm volatile(
        "mma.sync.aligned.m16n8k8.row.col.f32.tf32.tf32.f32 "
        "{%0,%1,%2,%3}, {%4,%5,%6,%7}, {%8,%9}, {%0,%1,%2,%3};"
        : "+f"(c[0]), "+f"(c[1]), "+f"(c[2]), "+f"(c[3])
        : "r"(a0), "r"(a1), "r"(a2), "r"(a3), "r"(b0), "r"(b1));
}

__device__ __forceinline__ void cp16(uint32_t dst, const float* src) {
    asm volatile("cp.async.cg.shared.global [%0], [%1], 16;" :: "r"(dst), "l"(src));
}
__device__ __forceinline__ void cp_commit() {
    asm volatile("cp.async.commit_group;");
}
template <int N>
__device__ __forceinline__ void cp_wait() {
    asm volatile("cp.async.wait_group %0;" :: "n"(N));
}

// ---------------------------------------------------------------------------
// Elementwise tf32 rounding (n divisible by 1024)
// ---------------------------------------------------------------------------
__global__ void __launch_bounds__(256)
round_tf32_kernel(const float* __restrict__ src, float* __restrict__ dst, int n)
{
    const int i = (blockIdx.x * 256 + threadIdx.x) * 4;
    if (i < n) {
        float4 v = *(const float4*)(src + i);
        v.x = roundtf(v.x); v.y = roundtf(v.y);
        v.z = roundtf(v.z); v.w = roundtf(v.w);
        *(float4*)(dst + i) = v;
    }
}

// ---------------------------------------------------------------------------
// tf32 GEMM, 4-stage cp.async pipeline.
// C[M,N] = A[M,K] @ W[N,K]^T + bias[N]. A/W pre-rounded to tf32.
// BM=BN=128, BK=16, 256 threads, warp tile 64x32.
// ---------------------------------------------------------------------------
template <bool ROUND>
__global__ void __launch_bounds__(256, 2)
gemm_tf32_pipe(int M, int N, int K,
               const float* __restrict__ A,
               const float* __restrict__ W,
               const float* __restrict__ bias,
               float* __restrict__ C)
{
    constexpr int BK = 16, PITCH = 20, STG = 4;
    constexpr int STAGE_W = 128 * PITCH;      // words per tile per stage
    extern __shared__ float smf[];
    float* As = smf;                          // [STG][128][PITCH]
    float* Ws = smf + STG * STAGE_W;
    const uint32_t sbase = (uint32_t)__cvta_generic_to_shared(smf);
    const uint32_t wbase = sbase + STG * STAGE_W * 4;

    const int tid  = threadIdx.x;
    const int lane = tid & 31;
    const int w    = tid >> 5;
    const int wr   = w >> 2;
    const int wc   = w & 3;
    const int m0   = blockIdx.y * 128;
    const int n0   = blockIdx.x * 128;
    const int g    = lane >> 2;
    const int tq   = lane & 3;

    // loader: thread -> (row, 8-float chunk pair)
    const int lrow = tid >> 1;                // 0..127
    const int lcol = (tid & 1) * 8;           // 0 or 8
    const float* Ap = A + (size_t)(m0 + lrow) * K + lcol;
    const float* Wp = W + (size_t)(n0 + lrow) * K + lcol;
    const uint32_t loff = (uint32_t)(lrow * PITCH + lcol) * 4;

#define G_ISSUE(s, ko)                                              \
    do {                                                            \
        uint32_t da = sbase + (uint32_t)(s) * STAGE_W * 4 + loff;   \
        cp16(da,      Ap + (ko));                                   \
        cp16(da + 16, Ap + (ko) + 4);                               \
        uint32_t dw = wbase + (uint32_t)(s) * STAGE_W * 4 + loff;   \
        cp16(dw,      Wp + (ko));                                   \
        cp16(dw + 16, Wp + (ko) + 4);                               \
        cp_commit();                                                \
    } while (0)

    float acc[4][4][4];
#pragma unroll
    for (int i = 0; i < 4; i++)
#pragma unroll
        for (int j = 0; j < 4; j++)
#pragma unroll
            for (int e = 0; e < 4; e++) acc[i][j][e] = 0.0f;

    const int nIter = K / BK;                 // 64
    G_ISSUE(0, 0);
    G_ISSUE(1, BK);
    G_ISSUE(2, 2 * BK);

    for (int it = 0; it < nIter; it++) {
        cp_wait<2>();
        __syncthreads();
        if (it + 3 < nIter) G_ISSUE((it + 3) & 3, (it + 3) * BK);

        const uint32_t* Ab = (const uint32_t*)(As + (it & 3) * STAGE_W);
        const uint32_t* Wb = (const uint32_t*)(Ws + (it & 3) * STAGE_W);

#pragma unroll
        for (int ks = 0; ks < 2; ks++) {
            const int kk = ks * 8;
            uint32_t af[4][4];
#pragma unroll
            for (int mi = 0; mi < 4; mi++) {
                const int rb = wr * 64 + mi * 16;
                af[mi][0] = Ab[(rb + g    ) * PITCH + kk + tq    ];
                af[mi][1] = Ab[(rb + g + 8) * PITCH + kk + tq    ];
                af[mi][2] = Ab[(rb + g    ) * PITCH + kk + tq + 4];
                af[mi][3] = Ab[(rb + g + 8) * PITCH + kk + tq + 4];
            }
            uint32_t bf[4][2];
#pragma unroll
            for (int ni = 0; ni < 4; ni++) {
                const int cb = wc * 32 + ni * 8;
                bf[ni][0] = Wb[(cb + g) * PITCH + kk + tq    ];
                bf[ni][1] = Wb[(cb + g) * PITCH + kk + tq + 4];
            }
#pragma unroll
            for (int mi = 0; mi < 4; mi++)
#pragma unroll
                for (int ni = 0; ni < 4; ni++)
                    mma_tf32(acc[mi][ni],
                             af[mi][0], af[mi][1], af[mi][2], af[mi][3],
                             bf[ni][0], bf[ni][1]);
        }
    }

#pragma unroll
    for (int mi = 0; mi < 4; mi++) {
        const int r0 = m0 + wr * 64 + mi * 16 + g;
#pragma unroll
        for (int ni = 0; ni < 4; ni++) {
            const int c = n0 + wc * 32 + ni * 8 + 2 * tq;
            const float b0v = bias[c], b1v = bias[c + 1];
            float2 o0, o1;
            if (ROUND) {
                o0 = make_float2(roundtf(acc[mi][ni][0] + b0v), roundtf(acc[mi][ni][1] + b1v));
                o1 = make_float2(roundtf(acc[mi][ni][2] + b0v), roundtf(acc[mi][ni][3] + b1v));
            } else {
                o0 = make_float2(acc[mi][ni][0] + b0v, acc[mi][ni][1] + b1v);
                o1 = make_float2(acc[mi][ni][2] + b0v, acc[mi][ni][3] + b1v);
            }
            *(float2*)(C + (size_t)r0 * N + c)       = o0;
            *(float2*)(C + (size_t)(r0 + 8) * N + c) = o1;
        }
    }
#undef G_ISSUE
}

// ---------------------------------------------------------------------------
// Flash attention tf32: 256 threads, 128 q rows/block, 64-key tiles,
// register-resident Q, 2-stage cp.async K/V pipeline (qkv pre-rounded).
// ---------------------------------------------------------------------------
#define QP 68
#define VP 72
#define KV_STAGE_W (64 * QP + 64 * VP)   // 8960 words per stage

__global__ void __launch_bounds__(256)
flash_attn_tf32(const float* __restrict__ qkv,
                const float* __restrict__ mask,
                float* __restrict__ out)
{
    extern __shared__ float smf[];
    float* QPs = smf;                          // [128][QP]: Q then reused as P
    // stage s: K at smf + 8704 + s*KV_STAGE_W, V at +64*QP further
    const uint32_t sbase = (uint32_t)__cvta_generic_to_shared(smf);

    const int tid  = threadIdx.x;
    const int lane = tid & 31;
    const int w    = tid >> 5;
    const int g    = lane >> 2;
    const int tq   = lane & 3;

    const int q0 = blockIdx.x * 128;
    const int h  = blockIdx.y;
    const int b  = blockIdx.z;
    const float scale = 0.125f;

    const float* base = qkv + (size_t)b * Sq * (3 * Dq) + (size_t)h * (3 * HDq);

    // K/V loader mapping: row = tid>>2 (0..63), cols (tid&3)*16 + {0,4,8,12}
    const int kvrow = tid >> 2;
    const int kvcol = (tid & 3) * 16;
    const float* Kp = base + 64  + (size_t)kvrow * (3 * Dq) + kvcol;
    const float* Vp = base + 128 + (size_t)kvrow * (3 * Dq) + kvcol;
    const uint32_t kOff = (uint32_t)(kvrow * QP + kvcol) * 4;
    const uint32_t vOff = (uint32_t)(64 * QP + kvrow * VP + kvcol) * 4;

#define F_ISSUE(s, ktile)                                                   \
    do {                                                                    \
        const size_t go = (size_t)(ktile) * 64 * (3 * Dq);                  \
        uint32_t sb = sbase + (uint32_t)(128 * QP + (s) * KV_STAGE_W) * 4;  \
        cp16(sb + kOff,      Kp + go);                                      \
        cp16(sb + kOff + 16, Kp + go + 4);                                  \
        cp16(sb + kOff + 32, Kp + go + 8);                                  \
        cp16(sb + kOff + 48, Kp + go + 12);                                 \
        cp16(sb + vOff,      Vp + go);                                      \
        cp16(sb + vOff + 16, Vp + go + 4);                                  \
        cp16(sb + vOff + 32, Vp + go + 8);                                  \
        cp16(sb + vOff + 48, Vp + go + 12);                                 \
        cp_commit();                                                        \
    } while (0)

    // kick off k-tile 0 immediately
    F_ISSUE(0, 0);

    // ---- Load Q tile (128x64, pre-rounded) into smem ----
    {
        const int r  = tid >> 4;
        const int c4 = (tid & 15) << 2;
#pragma unroll
        for (int rr = 0; rr < 8; rr++) {
            const int row = r + rr * 16;
            float4 v = *(const float4*)(base + (size_t)(q0 + row) * (3 * Dq) + c4);
            *(float4*)(QPs + row * QP + c4) = v;
        }
    }
    __syncthreads();

    // ---- Extract Q fragments (register-resident) ----
    uint32_t qa[8][4];
    {
        const uint32_t* Qu = (const uint32_t*)QPs;
        const int mb = w * 16;
#pragma unroll
        for (int ks = 0; ks < 8; ks++) {
            const int kk = ks * 8;
            qa[ks][0] = Qu[(mb + g)     * QP + kk + tq];
            qa[ks][1] = Qu[(mb + g + 8) * QP + kk + tq];
            qa[ks][2] = Qu[(mb + g)     * QP + kk + tq + 4];
            qa[ks][3] = Qu[(mb + g + 8) * QP + kk + tq + 4];
        }
    }
    __syncthreads();   // done reading Q; QPs may be reused as P

    float Oacc[8][4];
#pragma unroll
    for (int ni = 0; ni < 8; ni++)
#pragma unroll
        for (int e = 0; e < 4; e++) Oacc[ni][e] = 0.0f;
    float mrow0 = -INFINITY, mrow1 = -INFINITY;
    float lrow0 = 0.0f, lrow1 = 0.0f;

    const int r0 = w * 16 + g;
    const int r1 = r0 + 8;

    constexpr int NT = Sq / 64;
    for (int kt = 0; kt < NT; kt++) {
        const int k0t = kt * 64;

        cp_wait<0>();        // stage kt&1 data landed
        __syncthreads();     // + all warps done reading stage (kt+1)&1 (prev compute)
        if (kt + 1 < NT) F_ISSUE((kt + 1) & 1, kt + 1);

        const uint32_t* Ks = (const uint32_t*)(smf + 128 * QP + (kt & 1) * KV_STAGE_W);
        const uint32_t* Vs = Ks + 64 * QP;

        // ---- S = Q K^T ----
        float Sacc[8][4];
#pragma unroll
        for (int ni = 0; ni < 8; ni++)
#pragma unroll
            for (int e = 0; e < 4; e++) Sacc[ni][e] = 0.0f;

#pragma unroll
        for (int ks = 0; ks < 8; ks++) {
            const int kk = ks * 8;
#pragma unroll
            for (int ni = 0; ni < 8; ni++) {
                const int nb = ni * 8;
                uint32_t b0 = Ks[(nb + g) * QP + kk + tq];
                uint32_t b1 = Ks[(nb + g) * QP + kk + tq + 4];
                mma_tf32(Sacc[ni], qa[ks][0], qa[ks][1], qa[ks][2], qa[ks][3], b0, b1);
            }
        }

        // ---- scale + mask + online softmax ----
        float rmax0 = -INFINITY, rmax1 = -INFINITY;
#pragma unroll
        for (int ni = 0; ni < 8; ni++) {
            const int c = ni * 8 + 2 * tq;
            float2 mk0 = *(const float2*)(mask + (size_t)(q0 + r0) * Sq + k0t + c);
            float2 mk1 = *(const float2*)(mask + (size_t)(q0 + r1) * Sq + k0t + c);
            Sacc[ni][0] = Sacc[ni][0] * scale + mk0.x;
            Sacc[ni][1] = Sacc[ni][1] * scale + mk0.y;
            Sacc[ni][2] = Sacc[ni][2] * scale + mk1.x;
            Sacc[ni][3] = Sacc[ni][3] * scale + mk1.y;
            rmax0 = fmaxf(rmax0, fmaxf(Sacc[ni][0], Sacc[ni][1]));
            rmax1 = fmaxf(rmax1, fmaxf(Sacc[ni][2], Sacc[ni][3]));
        }
#pragma unroll
        for (int off = 1; off < 4; off <<= 1) {
            rmax0 = fmaxf(rmax0, __shfl_xor_sync(0xffffffffu, rmax0, off));
            rmax1 = fmaxf(rmax1, __shfl_xor_sync(0xffffffffu, rmax1, off));
        }
        const float mnew0 = fmaxf(mrow0, rmax0);
        const float mnew1 = fmaxf(mrow1, rmax1);
        const float alpha0 = __expf(mrow0 - mnew0);
        const float alpha1 = __expf(mrow1 - mnew1);
        float rs0 = 0.0f, rs1 = 0.0f;
#pragma unroll
        for (int ni = 0; ni < 8; ni++) {
            Sacc[ni][0] = __expf(Sacc[ni][0] - mnew0);
            Sacc[ni][1] = __expf(Sacc[ni][1] - mnew0);
            Sacc[ni][2] = __expf(Sacc[ni][2] - mnew1);
            Sacc[ni][3] = __expf(Sacc[ni][3] - mnew1);
            rs0 += Sacc[ni][0] + Sacc[ni][1];
            rs1 += Sacc[ni][2] + Sacc[ni][3];
        }
#pragma unroll
        for (int off = 1; off < 4; off <<= 1) {
            rs0 += __shfl_xor_sync(0xffffffffu, rs0, off);
            rs1 += __shfl_xor_sync(0xffffffffu, rs1, off);
        }
        lrow0 = lrow0 * alpha0 + rs0;
        lrow1 = lrow1 * alpha1 + rs1;
        mrow0 = mnew0;
        mrow1 = mnew1;
#pragma unroll
        for (int ni = 0; ni < 8; ni++) {
            Oacc[ni][0] *= alpha0; Oacc[ni][1] *= alpha0;
            Oacc[ni][2] *= alpha1; Oacc[ni][3] *= alpha1;
        }

        // ---- stash P (tf32) into this warp's private rows of QPs ----
        uint32_t* Pu = (uint32_t*)QPs;
        const int qr0 = w * 16 + g;
#pragma unroll
        for (int ni = 0; ni < 8; ni++) {
            const int c = ni * 8 + 2 * tq;
            uint2 s0 = make_uint2(f2tf32(Sacc[ni][0]), f2tf32(Sacc[ni][1]));
            uint2 s1 = make_uint2(f2tf32(Sacc[ni][2]), f2tf32(Sacc[ni][3]));
            *(uint2*)(Pu + (qr0)     * QP + c) = s0;
            *(uint2*)(Pu + (qr0 + 8) * QP + c) = s1;
        }
        __syncwarp();

        // ---- O += P V ----
        const int mb = w * 16;
#pragma unroll
        for (int ks = 0; ks < 8; ks++) {
            const int kk = ks * 8;
            uint32_t a0 = Pu[(mb + g)     * QP + kk + tq];
            uint32_t a1 = Pu[(mb + g + 8) * QP + kk + tq];
            uint32_t a2 = Pu[(mb + g)     * QP + kk + tq + 4];
            uint32_t a3 = Pu[(mb + g + 8) * QP + kk + tq + 4];
#pragma unroll
            for (int ni = 0; ni < 8; ni++) {
                const int nb = ni * 8;
                uint32_t b0 = Vs[(kk + tq)     * VP + nb + g];
                uint32_t b1 = Vs[(kk + tq + 4) * VP + nb + g];
                mma_tf32(Oacc[ni], a0, a1, a2, a3, b0, b1);
            }
        }
    }

    // ---- epilogue: normalize, round to tf32 (operand of out-proj), store ----
    const float inv0 = 1.0f / lrow0;
    const float inv1 = 1.0f / lrow1;
    float* obase = out + (size_t)b * Sq * Dq + (size_t)h * HDq;
#pragma unroll
    for (int ni = 0; ni < 8; ni++) {
        const int c = ni * 8 + 2 * tq;
        float2 o0 = make_float2(roundtf(Oacc[ni][0] * inv0), roundtf(Oacc[ni][1] * inv0));
        float2 o1 = make_float2(roundtf(Oacc[ni][2] * inv1), roundtf(Oacc[ni][3] * inv1));
        *(float2*)(obase + (size_t)(q0 + r0) * Dq + c) = o0;
        *(float2*)(obase + (size_t)(q0 + r1) * Dq + c) = o1;
    }
#undef F_ISSUE
}

// ---------------------------------------------------------------------------
extern "C" void kernel_launch(void* const* d_in, const int* in_sizes, int n_in,
                              void* d_out, int out_size)
{
    const float* x    = (const float*)d_in[0];
    const float* mask = (const float*)d_in[1];
    const float* Wqkv = (const float*)d_in[2];
    const float* bqkv = (const float*)d_in[3];
    const float* Wo   = (const float*)d_in[4];
    const float* bo   = (const float*)d_in[5];
    float* out = (float*)d_out;

    float *qkv, *vals, *xc, *wqkvc, *woc;
    cudaGetSymbolAddress((void**)&qkv,   g_qkv);
    cudaGetSymbolAddress((void**)&vals,  g_vals);
    cudaGetSymbolAddress((void**)&xc,    g_xc);
    cudaGetSymbolAddress((void**)&wqkvc, g_wqkvc);
    cudaGetSymbolAddress((void**)&woc,   g_woc);

    // 0) pre-round all GEMM operands to tf32
    {
        const int nx = Bq * Sq * Dq;         // 4M
        const int nq = 3 * Dq * Dq;          // 3M
        const int no = Dq * Dq;              // 1M
        round_tf32_kernel<<<nx / 1024, 256>>>(x, xc, nx);
        round_tf32_kernel<<<nq / 1024, 256>>>(Wqkv, wqkvc, nq);
        round_tf32_kernel<<<no / 1024, 256>>>(Wo, woc, no);
    }

    const int gemm_smem = 4 * 128 * 20 * 2 * (int)sizeof(float);   // 81920
    cudaFuncSetAttribute(gemm_tf32_pipe<true>,
                         cudaFuncAttributeMaxDynamicSharedMemorySize, gemm_smem);
    cudaFuncSetAttribute(gemm_tf32_pipe<false>,
                         cudaFuncAttributeMaxDynamicSharedMemorySize, gemm_smem);

    // 1) QKV projection (epilogue rounds output to tf32)
    {
        dim3 grid((3 * Dq) / 128, (Bq * Sq) / 128);
        gemm_tf32_pipe<true><<<grid, 256, gemm_smem>>>(Bq * Sq, 3 * Dq, Dq,
                                                       xc, wqkvc, bqkv, qkv);
    }

    // 2) Flash attention
    {
        const int smem = (128 * QP + 2 * KV_STAGE_W) * (int)sizeof(float); // 106496
        cudaFuncSetAttribute(flash_attn_tf32,
                             cudaFuncAttributeMaxDynamicSharedMemorySize, smem);
        dim3 grid(Sq / 128, Hq, Bq);
        flash_attn_tf32<<<grid, 256, smem>>>(qkv, mask, vals);
    }

    // 3) Output projection (plain fp32 epilogue)
    {
        dim3 grid(Dq / 128, (Bq * Sq) / 128);
        gemm_tf32_pipe<false><<<grid, 256, gemm_smem>>>(Bq * Sq, Dq, Dq,
                                                        vals, woc, bo, out);
    }
}